// round 3
// baseline (speedup 1.0000x reference)
#include <cuda_runtime.h>
#include <cstdint>

// Problem constants (fixed by the dataset)
#define BB 2
#define SS 2048
#define HH 2048
#define HD 128
#define NH 16
#define MM (BB*SS)   // 4096

// ---------------- scratch (static device globals — no allocation) ----------
__device__ float g_q[(size_t)BB*SS*HH];        // (B,S,H)   Q projection
__device__ float g_k[(size_t)BB*SS*HD];        // (B,S,hd)  K projection
__device__ float g_v[(size_t)BB*SS*HD];        // (B,S,hd)  V projection
__device__ float g_vt[(size_t)BB*HD*SS];       // (B,hd,S)  V transposed
__device__ float g_attn[(size_t)BB*SS*HH];     // (B,S,H)   attention output
__device__ float g_scores[(size_t)BB*NH*SS*SS];// (B,nh,S,S) scores/probs (512MB)

// ---------------- tf32 helpers ---------------------------------------------
__device__ __forceinline__ uint32_t f2tf32(float x) {
    uint32_t r; asm("cvt.rna.tf32.f32 %0, %1;" : "=r"(r) : "f"(x)); return r;
}
__device__ __forceinline__ void split_tf32(float x, float& hi, float& lo) {
    uint32_t h = f2tf32(x);
    hi = __uint_as_float(h);
    lo = x - hi;          // exact; hw truncates lo to tf32 inside mma (negligible)
}

#define MMA_TF32(d, a, b) asm volatile( \
    "mma.sync.aligned.m16n8k8.row.col.f32.tf32.tf32.f32 " \
    "{%0,%1,%2,%3}, {%4,%5,%6,%7}, {%8,%9}, {%0,%1,%2,%3};" \
    : "+f"((d)[0]), "+f"((d)[1]), "+f"((d)[2]), "+f"((d)[3]) \
    : "r"((a)[0]), "r"((a)[1]), "r"((a)[2]), "r"((a)[3]), \
      "r"((b)[0]), "r"((b)[1]))

// ---------------- batched strided NT GEMM, 3xTF32 --------------------------
// C[z][m][n] = alpha * sum_k A[z][m][k] * B[z][n][k]  (+ bias[n])
// Tile 128x128x16, 256 threads (8 warps as 2(m) x 4(n)), warp tile 64x32.
// SMEM k-major with stride 132 -> low-conflict fragment loads.
#define TBK 16
#define SSTR 132

__global__ __launch_bounds__(256) void gemm3_tf32(
    const float* __restrict__ A, const float* __restrict__ Bw,
    const float* __restrict__ bias, float* __restrict__ C,
    int M, int N, int K,
    long long lda, long long ldb, long long ldc,
    long long sAb, long long sAh, long long sBb, long long sBh,
    long long sCb, long long sCh, int nh, float alpha)
{
    __shared__ float Ahs[TBK][SSTR], Als[TBK][SSTR];
    __shared__ float Bhs[TBK][SSTR], Bls[TBK][SSTR];

    const int tid  = threadIdx.x;
    const int lane = tid & 31;
    const int warp = tid >> 5;
    const int gid  = lane >> 2;     // 0..7
    const int tig  = lane & 3;      // 0..3
    const int wm   = (warp >> 2) * 64;   // warp row offset (2 warps in m)
    const int wn   = (warp & 3) * 32;    // warp col offset (4 warps in n)

    const int z  = blockIdx.z;
    const int bb = z / nh;
    const int hh = z % nh;
    A  += (size_t)bb * sAb + (size_t)hh * sAh;
    Bw += (size_t)bb * sBb + (size_t)hh * sBh;
    C  += (size_t)bb * sCb + (size_t)hh * sCh;

    const int rowBase = blockIdx.y * 128;
    const int colBase = blockIdx.x * 128;

    float acc[4][4][4];
#pragma unroll
    for (int i = 0; i < 4; i++)
#pragma unroll
        for (int j = 0; j < 4; j++)
#pragma unroll
            for (int c = 0; c < 4; c++) acc[i][j][c] = 0.f;

    // tile loads: 512 float4 per operand tile, 2 per thread
    float4 pfa[2], pfb[2];
    auto loadTile = [&](int kt) {
#pragma unroll
        for (int i = 0; i < 2; i++) {
            int idx = tid + i * 256;        // 0..511
            int r   = idx >> 2;             // 0..127 (m or n row)
            int kc  = (idx & 3) * 4;        // 0,4,8,12
            pfa[i] = *reinterpret_cast<const float4*>(
                &A[(size_t)(rowBase + r) * lda + kt + kc]);
            pfb[i] = *reinterpret_cast<const float4*>(
                &Bw[(size_t)(colBase + r) * ldb + kt + kc]);
        }
    };
    auto stsTile = [&]() {
#pragma unroll
        for (int i = 0; i < 2; i++) {
            int idx = tid + i * 256;
            int r   = idx >> 2;
            int kc  = (idx & 3) * 4;
            float e[4] = {pfa[i].x, pfa[i].y, pfa[i].z, pfa[i].w};
#pragma unroll
            for (int j = 0; j < 4; j++) {
                float hi, lo; split_tf32(e[j], hi, lo);
                Ahs[kc + j][r] = hi; Als[kc + j][r] = lo;
            }
            float f[4] = {pfb[i].x, pfb[i].y, pfb[i].z, pfb[i].w};
#pragma unroll
            for (int j = 0; j < 4; j++) {
                float hi, lo; split_tf32(f[j], hi, lo);
                Bhs[kc + j][r] = hi; Bls[kc + j][r] = lo;
            }
        }
    };

    loadTile(0);
    for (int kt = 0; kt < K; kt += TBK) {
        stsTile();
        __syncthreads();
        if (kt + TBK < K) loadTile(kt + TBK);

#pragma unroll
        for (int ks = 0; ks < TBK; ks += 8) {
            // PTX m16n8k8.tf32 fragment layout (g=lane>>2, t=lane&3):
            //   a0=A[g][t]   a1=A[g+8][t]   a2=A[g][t+4]   a3=A[g+8][t+4]
            //   b0=B^T[g][t] b1=B^T[g][t+4]
            uint32_t ah[4][4], al[4][4], bh[4][2], bl[4][2];
#pragma unroll
            for (int mf = 0; mf < 4; mf++) {
                int m0 = wm + mf * 16 + gid;
                int k0 = ks + tig;
                ah[mf][0] = __float_as_uint(Ahs[k0    ][m0    ]);
                ah[mf][1] = __float_as_uint(Ahs[k0    ][m0 + 8]);
                ah[mf][2] = __float_as_uint(Ahs[k0 + 4][m0    ]);
                ah[mf][3] = __float_as_uint(Ahs[k0 + 4][m0 + 8]);
                al[mf][0] = __float_as_uint(Als[k0    ][m0    ]);
                al[mf][1] = __float_as_uint(Als[k0    ][m0 + 8]);
                al[mf][2] = __float_as_uint(Als[k0 + 4][m0    ]);
                al[mf][3] = __float_as_uint(Als[k0 + 4][m0 + 8]);
            }
#pragma unroll
            for (int nf = 0; nf < 4; nf++) {
                int n0 = wn + nf * 8 + gid;
                int k0 = ks + tig;
                bh[nf][0] = __float_as_uint(Bhs[k0    ][n0]);
                bh[nf][1] = __float_as_uint(Bhs[k0 + 4][n0]);
                bl[nf][0] = __float_as_uint(Bls[k0    ][n0]);
                bl[nf][1] = __float_as_uint(Bls[k0 + 4][n0]);
            }
#pragma unroll
            for (int mf = 0; mf < 4; mf++)
#pragma unroll
                for (int nf = 0; nf < 4; nf++) {
                    MMA_TF32(acc[mf][nf], ah[mf], bh[nf]);
                    MMA_TF32(acc[mf][nf], ah[mf], bl[nf]);
                    MMA_TF32(acc[mf][nf], al[mf], bh[nf]);
                }
        }
        __syncthreads();
    }

    // epilogue: c0=(g,2t) c1=(g,2t+1) c2=(g+8,2t) c3=(g+8,2t+1)
#pragma unroll
    for (int mf = 0; mf < 4; mf++) {
        int r0 = rowBase + wm + mf * 16 + gid;
#pragma unroll
        for (int nf = 0; nf < 4; nf++) {
            int c0 = colBase + wn + nf * 8 + 2 * tig;
            float b0 = 0.f, b1 = 0.f;
            if (bias) { b0 = bias[c0]; b1 = bias[c0 + 1]; }
            float2 v0 = make_float2(acc[mf][nf][0] * alpha + b0,
                                    acc[mf][nf][1] * alpha + b1);
            float2 v1 = make_float2(acc[mf][nf][2] * alpha + b0,
                                    acc[mf][nf][3] * alpha + b1);
            *reinterpret_cast<float2*>(&C[(size_t)r0 * ldc + c0])       = v0;
            *reinterpret_cast<float2*>(&C[(size_t)(r0 + 8) * ldc + c0]) = v1;
        }
    }
}

// ---------------- V transpose: (B,S,hd) -> (B,hd,S) ------------------------
__global__ __launch_bounds__(256) void transpose_v(
    const float* __restrict__ v, float* __restrict__ vt)
{
    __shared__ float t[32][33];
    int b  = blockIdx.z;
    int s0 = blockIdx.x * 32;
    int d0 = blockIdx.y * 32;
    int tx = threadIdx.x, ty = threadIdx.y;
#pragma unroll
    for (int i = 0; i < 4; i++)
        t[ty + 8 * i][tx] = v[((size_t)(b * SS) + s0 + ty + 8 * i) * HD + d0 + tx];
    __syncthreads();
#pragma unroll
    for (int i = 0; i < 4; i++)
        vt[((size_t)(b * HD) + d0 + ty + 8 * i) * SS + s0 + tx] = t[tx][ty + 8 * i];
}

// ---------------- masked softmax over score rows (in place) ----------------
// rows = B*NH*S = 65536, row length S = 2048. one warp per row.
__global__ __launch_bounds__(256) void softmax_rows(
    float* __restrict__ sc, const int* __restrict__ mask)
{
    int row  = blockIdx.x * 8 + (threadIdx.x >> 5);
    int lane = threadIdx.x & 31;
    int b    = row >> 15;                    // row / (NH*S)
    float* p = sc + (size_t)row * SS;
    const int* mrow = mask + (size_t)b * SS;

    float vals[64];
    float mx = -1e30f;
#pragma unroll
    for (int c = 0; c < 16; c++) {
        int j = c * 128 + lane * 4;
        float4 x = *reinterpret_cast<float4*>(p + j);
        if (mrow[j + 0] == 0) x.x = -1e30f;
        if (mrow[j + 1] == 0) x.y = -1e30f;
        if (mrow[j + 2] == 0) x.z = -1e30f;
        if (mrow[j + 3] == 0) x.w = -1e30f;
        vals[c*4+0] = x.x; vals[c*4+1] = x.y; vals[c*4+2] = x.z; vals[c*4+3] = x.w;
        mx = fmaxf(mx, fmaxf(fmaxf(x.x, x.y), fmaxf(x.z, x.w)));
    }
#pragma unroll
    for (int o = 16; o > 0; o >>= 1) mx = fmaxf(mx, __shfl_xor_sync(~0u, mx, o));

    float sum = 0.f;
#pragma unroll
    for (int i = 0; i < 64; i++) {
        float e = __expf(vals[i] - mx);
        vals[i] = e;
        sum += e;
    }
#pragma unroll
    for (int o = 16; o > 0; o >>= 1) sum += __shfl_xor_sync(~0u, sum, o);
    float inv = 1.0f / sum;

#pragma unroll
    for (int c = 0; c < 16; c++) {
        int j = c * 128 + lane * 4;
        float4 x = make_float4(vals[c*4+0]*inv, vals[c*4+1]*inv,
                               vals[c*4+2]*inv, vals[c*4+3]*inv);
        *reinterpret_cast<float4*>(p + j) = x;
    }
}

// ---------------- launch ---------------------------------------------------
extern "C" void kernel_launch(void* const* d_in, const int* in_sizes, int n_in,
                              void* d_out, int out_size)
{
    const float* hidden = (const float*)d_in[0];
    const int*   mask   = (const int*)  d_in[1];
    const float* Wq = (const float*)d_in[2];
    const float* bq = (const float*)d_in[3];
    const float* Wk = (const float*)d_in[4];
    const float* bk = (const float*)d_in[5];
    const float* Wv = (const float*)d_in[6];
    const float* bv = (const float*)d_in[7];
    const float* Wo = (const float*)d_in[8];
    const float* bo = (const float*)d_in[9];
    float* out = (float*)d_out;

    float *q, *k, *v, *vt, *attn, *scores;
    cudaGetSymbolAddress((void**)&q,      g_q);
    cudaGetSymbolAddress((void**)&k,      g_k);
    cudaGetSymbolAddress((void**)&v,      g_v);
    cudaGetSymbolAddress((void**)&vt,     g_vt);
    cudaGetSymbolAddress((void**)&attn,   g_attn);
    cudaGetSymbolAddress((void**)&scores, g_scores);

    const float ascale = 0.08838834764831845f;   // 1/sqrt(128)

    // Q projection: (4096,2048) = hidden @ Wq^T + bq
    gemm3_tf32<<<dim3(16, 32, 1), 256>>>(hidden, Wq, bq, q,
        MM, HH, HH, HH, HH, HH, 0, 0, 0, 0, 0, 0, 1, 1.f);
    // K / V projections: (4096,128)
    gemm3_tf32<<<dim3(1, 32, 1), 256>>>(hidden, Wk, bk, k,
        MM, HD, HH, HH, HH, HD, 0, 0, 0, 0, 0, 0, 1, 1.f);
    gemm3_tf32<<<dim3(1, 32, 1), 256>>>(hidden, Wv, bv, v,
        MM, HD, HH, HH, HH, HD, 0, 0, 0, 0, 0, 0, 1, 1.f);
    // V transpose
    transpose_v<<<dim3(SS/32, HD/32, BB), dim3(32, 8)>>>(v, vt);
    // scores[b,h] = alpha * Q[b,:,h,:] @ K[b]^T   (M=S, N=S, K=hd)
    gemm3_tf32<<<dim3(16, 16, BB*NH), 256>>>(q, k, nullptr, scores,
        SS, SS, HD,
        HH, HD, SS,
        (long long)SS*HH, HD,
        (long long)SS*HD, 0,
        (long long)NH*SS*SS, (long long)SS*SS, NH, ascale);
    // softmax (masked, in place)
    softmax_rows<<<(BB*NH*SS)/8, 256>>>(scores, mask);
    // attn[b,:,h,:] = P[b,h] @ V[b]   (M=S, N=hd, K=S; B operand = Vt, NT)
    gemm3_tf32<<<dim3(1, 16, BB*NH), 256>>>(scores, vt, nullptr, attn,
        SS, HD, SS,
        SS, SS, HH,
        (long long)NH*SS*SS, (long long)SS*SS,
        (long long)HD*SS, 0,
        (long long)SS*HH, HD, NH, 1.f);
    // output projection -> d_out
    gemm3_tf32<<<dim3(16, 32, 1), 256>>>(attn, Wo, bo, out,
        MM, HH, HH, HH, HH, HH, 0, 0, 0, 0, 0, 0, 1, 1.f);
}

// round 6
// speedup vs baseline: 3.2221x; 3.2221x over previous
#include <cuda_runtime.h>
#include <cuda_fp16.h>
#include <cstdint>
#include <cstring>

// Problem constants (fixed by the dataset)
#define BB 2
#define SS 2048
#define HH 2048
#define HD 128
#define NH 16
#define MM (BB*SS)   // 4096

// ---------------- scratch (static device globals — no allocation) ----------
__device__ float g_q[(size_t)BB*SS*HH];        // (B,S,H)   Q projection
__device__ float g_k[(size_t)BB*SS*HD];        // (B,S,hd)  K projection
__device__ float g_v[(size_t)BB*SS*HD];        // (B,S,hd)  V projection
__device__ float g_vt[(size_t)BB*HD*SS];       // (B,hd,S)  V transposed
__device__ float g_attn[(size_t)BB*SS*HH];     // (B,S,H)   attention output
__device__ float g_scores[(size_t)BB*NH*SS*SS];// (B,nh,S,S) scores/probs (512MB)

// ---------------- helpers ---------------------------------------------------
__device__ __forceinline__ uint32_t smem_u32(const void* p) {
    uint32_t a;
    asm("{ .reg .u64 t; cvta.to.shared.u64 t, %1; cvt.u32.u64 %0, t; }"
        : "=r"(a) : "l"(p));
    return a;
}

#define MMA_F16(d, a0, a1, a2, a3, b0, b1) asm volatile( \
    "mma.sync.aligned.m16n8k16.row.col.f32.f16.f16.f32 " \
    "{%0,%1,%2,%3}, {%4,%5,%6,%7}, {%8,%9}, {%0,%1,%2,%3};" \
    : "+f"((d)[0]), "+f"((d)[1]), "+f"((d)[2]), "+f"((d)[3]) \
    : "r"(a0), "r"(a1), "r"(a2), "r"(a3), "r"(b0), "r"(b1))

#define LDSM_X4(r0, r1, r2, r3, addr) asm volatile( \
    "ldmatrix.sync.aligned.m8n8.x4.shared.b16 {%0,%1,%2,%3}, [%4];" \
    : "=r"(r0), "=r"(r1), "=r"(r2), "=r"(r3) : "r"(addr))

__device__ __forceinline__ uint32_t h2_as_u32(__half x, __half y) {
    __half2 t = __halves2half2(x, y);
    uint32_t u; memcpy(&u, &t, 4); return u;
}

// ---------------- fp16x3 mma.sync batched strided NT GEMM ------------------
// C[z][m][n] = alpha * sum_k A[z][m][k]*B[z][n][k] (+ bias[n])
// CTA tile 128x128, K-chunk 32. 256 threads = 8 warps (2m x 4n), warp 64x32.
// SMEM: 4 fp16 tiles (Ah,Al,Bh,Bl), 128 rows x 32 halves, row stride 80B
// (80 mod 128 cycles all eight 16B banks -> conflict-free ldmatrix).
#define RSTR 80
#define T_AH 0
#define T_AL 10240
#define T_BH 20480
#define T_BL 30720

__global__ __launch_bounds__(256)
void gemm_hmma(const float* __restrict__ A, const float* __restrict__ Bw,
               const float* __restrict__ bias, float* __restrict__ C,
               int K, long long lda, long long ldb, long long ldc,
               long long sAb, long long sAh, long long sBb, long long sBh,
               long long sCb, long long sCh, int nh, float alpha)
{
    __shared__ __align__(16) unsigned char smem[40960];
    const uint32_t sb = smem_u32(smem);

    const int tid  = threadIdx.x;
    const int lane = tid & 31;
    const int warp = tid >> 5;
    const int gid  = lane >> 2;          // 0..7
    const int tig  = lane & 3;           // 0..3
    const int wm   = (warp >> 2) * 64;   // 2 warps in m
    const int wn   = (warp & 3) * 32;    // 4 warps in n

    const int z  = blockIdx.z;
    const int bb = z / nh;
    const int hh = z % nh;
    A  += (size_t)bb * sAb + (size_t)hh * sAh;
    Bw += (size_t)bb * sBb + (size_t)hh * sBh;
    C  += (size_t)bb * sCb + (size_t)hh * sCh;

    const int rowBase = blockIdx.y * 128;
    const int colBase = blockIdx.x * 128;

    float acc[4][4][4];
#pragma unroll
    for (int i = 0; i < 4; i++)
#pragma unroll
        for (int j = 0; j < 4; j++)
#pragma unroll
            for (int c = 0; c < 4; c++) acc[i][j][c] = 0.f;

    // per-lane ldmatrix base addresses (A: lanes 0-15 rows, 16-31 k+8;
    // B x4 covers two n-frags: lanes (0-7,8-15,16-23,24-31) =
    //   (nf0 k0, nf0 k0+8, nf1 k0, nf1 k0+8))
    const uint32_t aBase = sb + (uint32_t)((wm + (lane & 15)) * RSTR
                          + ((lane >> 4) & 1) * 16);
    const uint32_t bBase = sb + (uint32_t)((wn + ((lane >> 4) & 1) * 8
                          + (lane & 7)) * RSTR + ((lane >> 3) & 1) * 16);

    // chunk loads: 128 rows x 8 float4 per matrix -> 4 float4/thread each
    const int ldRow = tid >> 3;          // base row for this thread
    const int ldF4  = tid & 7;           // f4 group
    float4 pa[4], pb[4];
    auto loadChunk = [&](int c) {
        const int kt = c << 5;
#pragma unroll
        for (int i = 0; i < 4; i++) {
            int row = ldRow + i * 32;
            pa[i] = *reinterpret_cast<const float4*>(
                &A[(size_t)(rowBase + row) * lda + kt + ldF4 * 4]);
            pb[i] = *reinterpret_cast<const float4*>(
                &Bw[(size_t)(colBase + row) * ldb + kt + ldF4 * 4]);
        }
    };
    auto stsChunk = [&]() {
#pragma unroll
        for (int i = 0; i < 4; i++) {
            int row = ldRow + i * 32;
            uint32_t off = (uint32_t)(row * RSTR + ldF4 * 8);
            {
                float4 v = pa[i];
                __half hx = __float2half_rn(v.x), hy = __float2half_rn(v.y);
                __half hz = __float2half_rn(v.z), hw = __float2half_rn(v.w);
                *reinterpret_cast<uint2*>(smem + T_AH + off) =
                    make_uint2(h2_as_u32(hx, hy), h2_as_u32(hz, hw));
                *reinterpret_cast<uint2*>(smem + T_AL + off) = make_uint2(
                    h2_as_u32(__float2half_rn(v.x - __half2float(hx)),
                              __float2half_rn(v.y - __half2float(hy))),
                    h2_as_u32(__float2half_rn(v.z - __half2float(hz)),
                              __float2half_rn(v.w - __half2float(hw))));
            }
            {
                float4 v = pb[i];
                __half hx = __float2half_rn(v.x), hy = __float2half_rn(v.y);
                __half hz = __float2half_rn(v.z), hw = __float2half_rn(v.w);
                *reinterpret_cast<uint2*>(smem + T_BH + off) =
                    make_uint2(h2_as_u32(hx, hy), h2_as_u32(hz, hw));
                *reinterpret_cast<uint2*>(smem + T_BL + off) = make_uint2(
                    h2_as_u32(__float2half_rn(v.x - __half2float(hx)),
                              __float2half_rn(v.y - __half2float(hy))),
                    h2_as_u32(__float2half_rn(v.z - __half2float(hz)),
                              __float2half_rn(v.w - __half2float(hw))));
            }
        }
    };

    const int nchunks = K >> 5;
    loadChunk(0);
    for (int c = 0; c < nchunks; c++) {
        stsChunk();
        __syncthreads();
        if (c + 1 < nchunks) loadChunk(c + 1);

#pragma unroll
        for (int ks = 0; ks < 2; ks++) {
            const uint32_t ko = ks * 32;       // 16 halves = 32 bytes
            uint32_t ah[4][4], al[4][4], bh[4][2], bl[4][2];
#pragma unroll
            for (int mf = 0; mf < 4; mf++) {
                uint32_t a = aBase + mf * (16 * RSTR) + ko;
                LDSM_X4(ah[mf][0], ah[mf][1], ah[mf][2], ah[mf][3], a + T_AH);
                LDSM_X4(al[mf][0], al[mf][1], al[mf][2], al[mf][3], a + T_AL);
            }
#pragma unroll
            for (int nfp = 0; nfp < 2; nfp++) {
                uint32_t b = bBase + nfp * (16 * RSTR) + ko;
                LDSM_X4(bh[2*nfp][0], bh[2*nfp][1], bh[2*nfp+1][0], bh[2*nfp+1][1],
                        b + T_BH);
                LDSM_X4(bl[2*nfp][0], bl[2*nfp][1], bl[2*nfp+1][0], bl[2*nfp+1][1],
                        b + T_BL);
            }
#pragma unroll
            for (int mf = 0; mf < 4; mf++)
#pragma unroll
                for (int nf = 0; nf < 4; nf++) {
                    MMA_F16(acc[mf][nf], ah[mf][0], ah[mf][1], ah[mf][2], ah[mf][3],
                            bh[nf][0], bh[nf][1]);
                    MMA_F16(acc[mf][nf], ah[mf][0], ah[mf][1], ah[mf][2], ah[mf][3],
                            bl[nf][0], bl[nf][1]);
                    MMA_F16(acc[mf][nf], al[mf][0], al[mf][1], al[mf][2], al[mf][3],
                            bh[nf][0], bh[nf][1]);
                }
        }
        __syncthreads();
    }

    // epilogue: c0=(g,2t) c1=(g,2t+1) c2=(g+8,2t) c3=(g+8,2t+1)
#pragma unroll
    for (int mf = 0; mf < 4; mf++) {
        int r0 = rowBase + wm + mf * 16 + gid;
#pragma unroll
        for (int nf = 0; nf < 4; nf++) {
            int c0 = colBase + wn + nf * 8 + 2 * tig;
            float b0 = 0.f, b1 = 0.f;
            if (bias) { b0 = bias[c0]; b1 = bias[c0 + 1]; }
            float2 v0 = make_float2(acc[mf][nf][0] * alpha + b0,
                                    acc[mf][nf][1] * alpha + b1);
            float2 v1 = make_float2(acc[mf][nf][2] * alpha + b0,
                                    acc[mf][nf][3] * alpha + b1);
            *reinterpret_cast<float2*>(&C[(size_t)r0 * ldc + c0])       = v0;
            *reinterpret_cast<float2*>(&C[(size_t)(r0 + 8) * ldc + c0]) = v1;
        }
    }
}

// ---------------- V transpose: (B,S,hd) -> (B,hd,S) ------------------------
__global__ __launch_bounds__(256) void transpose_v(
    const float* __restrict__ v, float* __restrict__ vt)
{
    __shared__ float t[32][33];
    int b  = blockIdx.z;
    int s0 = blockIdx.x * 32;
    int d0 = blockIdx.y * 32;
    int tx = threadIdx.x, ty = threadIdx.y;
#pragma unroll
    for (int i = 0; i < 4; i++)
        t[ty + 8 * i][tx] = v[((size_t)(b * SS) + s0 + ty + 8 * i) * HD + d0 + tx];
    __syncthreads();
#pragma unroll
    for (int i = 0; i < 4; i++)
        vt[((size_t)(b * HD) + d0 + ty + 8 * i) * SS + s0 + tx] = t[tx][ty + 8 * i];
}

// ---------------- masked softmax over score rows (in place) ----------------
__global__ __launch_bounds__(256) void softmax_rows(
    float* __restrict__ sc, const int* __restrict__ mask)
{
    int row  = blockIdx.x * 8 + (threadIdx.x >> 5);
    int lane = threadIdx.x & 31;
    int b    = row >> 15;
    float* p = sc + (size_t)row * SS;
    const int* mrow = mask + (size_t)b * SS;

    float vals[64];
    float mx = -1e30f;
#pragma unroll
    for (int c = 0; c < 16; c++) {
        int j = c * 128 + lane * 4;
        float4 x = *reinterpret_cast<float4*>(p + j);
        if (mrow[j + 0] == 0) x.x = -1e30f;
        if (mrow[j + 1] == 0) x.y = -1e30f;
        if (mrow[j + 2] == 0) x.z = -1e30f;
        if (mrow[j + 3] == 0) x.w = -1e30f;
        vals[c*4+0] = x.x; vals[c*4+1] = x.y; vals[c*4+2] = x.z; vals[c*4+3] = x.w;
        mx = fmaxf(mx, fmaxf(fmaxf(x.x, x.y), fmaxf(x.z, x.w)));
    }
#pragma unroll
    for (int o = 16; o > 0; o >>= 1) mx = fmaxf(mx, __shfl_xor_sync(~0u, mx, o));

    float sum = 0.f;
#pragma unroll
    for (int i = 0; i < 64; i++) {
        float e = __expf(vals[i] - mx);
        vals[i] = e;
        sum += e;
    }
#pragma unroll
    for (int o = 16; o > 0; o >>= 1) sum += __shfl_xor_sync(~0u, sum, o);
    float inv = 1.0f / sum;

#pragma unroll
    for (int c = 0; c < 16; c++) {
        int j = c * 128 + lane * 4;
        float4 x = make_float4(vals[c*4+0]*inv, vals[c*4+1]*inv,
                               vals[c*4+2]*inv, vals[c*4+3]*inv);
        *reinterpret_cast<float4*>(p + j) = x;
    }
}

// ---------------- launch ---------------------------------------------------
extern "C" void kernel_launch(void* const* d_in, const int* in_sizes, int n_in,
                              void* d_out, int out_size)
{
    const float* hidden = (const float*)d_in[0];
    const int*   mask   = (const int*)  d_in[1];
    const float* Wq = (const float*)d_in[2];
    const float* bq = (const float*)d_in[3];
    const float* Wk = (const float*)d_in[4];
    const float* bk = (const float*)d_in[5];
    const float* Wv = (const float*)d_in[6];
    const float* bv = (const float*)d_in[7];
    const float* Wo = (const float*)d_in[8];
    const float* bo = (const float*)d_in[9];
    float* out = (float*)d_out;

    float *q, *k, *v, *vt, *attn, *scores;
    cudaGetSymbolAddress((void**)&q,      g_q);
    cudaGetSymbolAddress((void**)&k,      g_k);
    cudaGetSymbolAddress((void**)&v,      g_v);
    cudaGetSymbolAddress((void**)&vt,     g_vt);
    cudaGetSymbolAddress((void**)&attn,   g_attn);
    cudaGetSymbolAddress((void**)&scores, g_scores);

    const float ascale = 0.08838834764831845f;   // 1/sqrt(128)

    // Q projection
    gemm_hmma<<<dim3(16, 32, 1), 256>>>(hidden, Wq, bq, q,
        HH, HH, HH, HH, 0, 0, 0, 0, 0, 0, 1, 1.f);
    // K / V projections
    gemm_hmma<<<dim3(1, 32, 1), 256>>>(hidden, Wk, bk, k,
        HH, HH, HH, HD, 0, 0, 0, 0, 0, 0, 1, 1.f);
    gemm_hmma<<<dim3(1, 32, 1), 256>>>(hidden, Wv, bv, v,
        HH, HH, HH, HD, 0, 0, 0, 0, 0, 0, 1, 1.f);
    // V transpose
    transpose_v<<<dim3(SS/32, HD/32, BB), dim3(32, 8)>>>(v, vt);
    // scores[b,h] = alpha * Q[b,:,h,:] @ K[b]^T
    gemm_hmma<<<dim3(16, 16, BB*NH), 256>>>(q, k, nullptr, scores,
        HD, HH, HD, SS,
        (long long)SS*HH, HD,
        (long long)SS*HD, 0,
        (long long)NH*SS*SS, (long long)SS*SS, NH, ascale);
    // softmax (masked, in place)
    softmax_rows<<<(BB*NH*SS)/8, 256>>>(scores, mask);
    // attn[b,:,h,:] = P[b,h] @ V[b]
    gemm_hmma<<<dim3(1, 16, BB*NH), 256>>>(scores, vt, nullptr, attn,
        SS, SS, SS, HH,
        (long long)NH*SS*SS, (long long)SS*SS,
        (long long)HD*SS, 0,
        (long long)SS*HH, HD, NH, 1.f);
    // output projection
    gemm_hmma<<<dim3(16, 32, 1), 256>>>(attn, Wo, bo, out,
        HH, HH, HH, HH, 0, 0, 0, 0, 0, 0, 1, 1.f);
}

// round 7
// speedup vs baseline: 3.6380x; 1.1291x over previous
#include <cuda_runtime.h>
#include <cuda_fp16.h>
#include <cstdint>
#include <cstring>

// Problem constants (fixed by the dataset)
#define BB 2
#define SS 2048
#define HH 2048
#define HD 128
#define NH 16
#define MM (BB*SS)   // 4096

// ---------------- scratch (static device globals — no allocation) ----------
__device__ __half g_qh[(size_t)BB*SS*HH];   // Q projection hi (B,S,H)
__device__ __half g_ql[(size_t)BB*SS*HH];   // Q projection lo
__device__ __half g_kh[(size_t)BB*SS*HD];   // K hi (B,S,hd)
__device__ __half g_kl[(size_t)BB*SS*HD];
__device__ __half g_vh[(size_t)BB*SS*HD];   // V hi
__device__ __half g_vl[(size_t)BB*SS*HD];
__device__ float  g_attn[(size_t)BB*SS*HH]; // attention output (B,S,H)
__device__ float  g_maskb[(size_t)BB*SS];   // mask bias: 0 or -1e30

// ---------------- helpers ---------------------------------------------------
__device__ __forceinline__ uint32_t smem_u32(const void* p) {
    uint32_t a;
    asm("{ .reg .u64 t; cvta.to.shared.u64 t, %1; cvt.u32.u64 %0, t; }"
        : "=r"(a) : "l"(p));
    return a;
}

#define MMA_F16(d, a0, a1, a2, a3, b0, b1) asm volatile( \
    "mma.sync.aligned.m16n8k16.row.col.f32.f16.f16.f32 " \
    "{%0,%1,%2,%3}, {%4,%5,%6,%7}, {%8,%9}, {%0,%1,%2,%3};" \
    : "+f"((d)[0]), "+f"((d)[1]), "+f"((d)[2]), "+f"((d)[3]) \
    : "r"(a0), "r"(a1), "r"(a2), "r"(a3), "r"(b0), "r"(b1))

#define LDSM_X4(r0, r1, r2, r3, addr) asm volatile( \
    "ldmatrix.sync.aligned.m8n8.x4.shared.b16 {%0,%1,%2,%3}, [%4];" \
    : "=r"(r0), "=r"(r1), "=r"(r2), "=r"(r3) : "r"(addr))

#define LDSM_X4_T(r0, r1, r2, r3, addr) asm volatile( \
    "ldmatrix.sync.aligned.m8n8.x4.trans.shared.b16 {%0,%1,%2,%3}, [%4];" \
    : "=r"(r0), "=r"(r1), "=r"(r2), "=r"(r3) : "r"(addr))

#define CP_ASYNC16(s, g) asm volatile( \
    "cp.async.ca.shared.global [%0], [%1], 16;" :: "r"(s), "l"(g))
#define CP_ASYNC4(s, g) asm volatile( \
    "cp.async.ca.shared.global [%0], [%1], 4;" :: "r"(s), "l"(g))
#define CP_COMMIT() asm volatile("cp.async.commit_group;")
#define CP_WAIT0() asm volatile("cp.async.wait_group 0;")
#define CP_WAIT1() asm volatile("cp.async.wait_group 1;")

__device__ __forceinline__ uint32_t h2_as_u32(__half x, __half y) {
    __half2 t = __halves2half2(x, y);
    uint32_t u; memcpy(&u, &t, 4); return u;
}

// ---------------- fp16x3 mma.sync batched strided NT GEMM ------------------
// C[z][m][n] = alpha * sum_k A[z][m][k]*B[z][n][k] (+ bias[n])
// fp32 A/B in gmem, split to fp16 hi/lo in smem. Output either fp32 C, or
// fp16 hi/lo pair (Ch, Cl) for downstream 3xFP16 consumers.
#define RSTR 80
#define T_AH 0
#define T_AL 10240
#define T_BH 20480
#define T_BL 30720

__global__ __launch_bounds__(256)
void gemm_hmma(const float* __restrict__ A, const float* __restrict__ Bw,
               const float* __restrict__ bias, float* __restrict__ C,
               __half* __restrict__ Ch, __half* __restrict__ Cl,
               int K, long long lda, long long ldb, long long ldc,
               float alpha)
{
    __shared__ __align__(16) unsigned char smem[40960];
    const uint32_t sb = smem_u32(smem);

    const int tid  = threadIdx.x;
    const int lane = tid & 31;
    const int warp = tid >> 5;
    const int gid  = lane >> 2;
    const int tig  = lane & 3;
    const int wm   = (warp >> 2) * 64;
    const int wn   = (warp & 3) * 32;

    const int rowBase = blockIdx.y * 128;
    const int colBase = blockIdx.x * 128;

    float acc[4][4][4];
#pragma unroll
    for (int i = 0; i < 4; i++)
#pragma unroll
        for (int j = 0; j < 4; j++)
#pragma unroll
            for (int c = 0; c < 4; c++) acc[i][j][c] = 0.f;

    const uint32_t aBase = sb + (uint32_t)((wm + (lane & 15)) * RSTR
                          + ((lane >> 4) & 1) * 16);
    const uint32_t bBase = sb + (uint32_t)((wn + ((lane >> 4) & 1) * 8
                          + (lane & 7)) * RSTR + ((lane >> 3) & 1) * 16);

    const int ldRow = tid >> 3;
    const int ldF4  = tid & 7;
    float4 pa[4], pb[4];
    auto loadChunk = [&](int c) {
        const int kt = c << 5;
#pragma unroll
        for (int i = 0; i < 4; i++) {
            int row = ldRow + i * 32;
            pa[i] = *reinterpret_cast<const float4*>(
                &A[(size_t)(rowBase + row) * lda + kt + ldF4 * 4]);
            pb[i] = *reinterpret_cast<const float4*>(
                &Bw[(size_t)(colBase + row) * ldb + kt + ldF4 * 4]);
        }
    };
    auto stsChunk = [&]() {
#pragma unroll
        for (int i = 0; i < 4; i++) {
            int row = ldRow + i * 32;
            uint32_t off = (uint32_t)(row * RSTR + ldF4 * 8);
            {
                float4 v = pa[i];
                __half hx = __float2half_rn(v.x), hy = __float2half_rn(v.y);
                __half hz = __float2half_rn(v.z), hw = __float2half_rn(v.w);
                *reinterpret_cast<uint2*>(smem + T_AH + off) =
                    make_uint2(h2_as_u32(hx, hy), h2_as_u32(hz, hw));
                *reinterpret_cast<uint2*>(smem + T_AL + off) = make_uint2(
                    h2_as_u32(__float2half_rn(v.x - __half2float(hx)),
                              __float2half_rn(v.y - __half2float(hy))),
                    h2_as_u32(__float2half_rn(v.z - __half2float(hz)),
                              __float2half_rn(v.w - __half2float(hw))));
            }
            {
                float4 v = pb[i];
                __half hx = __float2half_rn(v.x), hy = __float2half_rn(v.y);
                __half hz = __float2half_rn(v.z), hw = __float2half_rn(v.w);
                *reinterpret_cast<uint2*>(smem + T_BH + off) =
                    make_uint2(h2_as_u32(hx, hy), h2_as_u32(hz, hw));
                *reinterpret_cast<uint2*>(smem + T_BL + off) = make_uint2(
                    h2_as_u32(__float2half_rn(v.x - __half2float(hx)),
                              __float2half_rn(v.y - __half2float(hy))),
                    h2_as_u32(__float2half_rn(v.z - __half2float(hz)),
                              __float2half_rn(v.w - __half2float(hw))));
            }
        }
    };

    const int nchunks = K >> 5;
    loadChunk(0);
    for (int c = 0; c < nchunks; c++) {
        stsChunk();
        __syncthreads();
        if (c + 1 < nchunks) loadChunk(c + 1);

#pragma unroll
        for (int ks = 0; ks < 2; ks++) {
            const uint32_t ko = ks * 32;
            uint32_t ah[4][4], al[4][4], bh[4][2], bl[4][2];
#pragma unroll
            for (int mf = 0; mf < 4; mf++) {
                uint32_t a = aBase + mf * (16 * RSTR) + ko;
                LDSM_X4(ah[mf][0], ah[mf][1], ah[mf][2], ah[mf][3], a + T_AH);
                LDSM_X4(al[mf][0], al[mf][1], al[mf][2], al[mf][3], a + T_AL);
            }
#pragma unroll
            for (int nfp = 0; nfp < 2; nfp++) {
                uint32_t b = bBase + nfp * (16 * RSTR) + ko;
                LDSM_X4(bh[2*nfp][0], bh[2*nfp][1], bh[2*nfp+1][0], bh[2*nfp+1][1],
                        b + T_BH);
                LDSM_X4(bl[2*nfp][0], bl[2*nfp][1], bl[2*nfp+1][0], bl[2*nfp+1][1],
                        b + T_BL);
            }
#pragma unroll
            for (int mf = 0; mf < 4; mf++)
#pragma unroll
                for (int nf = 0; nf < 4; nf++) {
                    MMA_F16(acc[mf][nf], ah[mf][0], ah[mf][1], ah[mf][2], ah[mf][3],
                            bh[nf][0], bh[nf][1]);
                    MMA_F16(acc[mf][nf], ah[mf][0], ah[mf][1], ah[mf][2], ah[mf][3],
                            bl[nf][0], bl[nf][1]);
                    MMA_F16(acc[mf][nf], al[mf][0], al[mf][1], al[mf][2], al[mf][3],
                            bh[nf][0], bh[nf][1]);
                }
        }
        __syncthreads();
    }

#pragma unroll
    for (int mf = 0; mf < 4; mf++) {
        int r0 = rowBase + wm + mf * 16 + gid;
#pragma unroll
        for (int nf = 0; nf < 4; nf++) {
            int c0 = colBase + wn + nf * 8 + 2 * tig;
            float b0 = 0.f, b1 = 0.f;
            if (bias) { b0 = bias[c0]; b1 = bias[c0 + 1]; }
            float v00 = acc[mf][nf][0] * alpha + b0;
            float v01 = acc[mf][nf][1] * alpha + b1;
            float v10 = acc[mf][nf][2] * alpha + b0;
            float v11 = acc[mf][nf][3] * alpha + b1;
            if (Ch) {
                __half h00 = __float2half_rn(v00), h01 = __float2half_rn(v01);
                __half h10 = __float2half_rn(v10), h11 = __float2half_rn(v11);
                *reinterpret_cast<uint32_t*>(&Ch[(size_t)r0 * ldc + c0]) =
                    h2_as_u32(h00, h01);
                *reinterpret_cast<uint32_t*>(&Ch[(size_t)(r0 + 8) * ldc + c0]) =
                    h2_as_u32(h10, h11);
                *reinterpret_cast<uint32_t*>(&Cl[(size_t)r0 * ldc + c0]) =
                    h2_as_u32(__float2half_rn(v00 - __half2float(h00)),
                              __float2half_rn(v01 - __half2float(h01)));
                *reinterpret_cast<uint32_t*>(&Cl[(size_t)(r0 + 8) * ldc + c0]) =
                    h2_as_u32(__float2half_rn(v10 - __half2float(h10)),
                              __float2half_rn(v11 - __half2float(h11)));
            } else {
                *reinterpret_cast<float2*>(&C[(size_t)r0 * ldc + c0]) =
                    make_float2(v00, v01);
                *reinterpret_cast<float2*>(&C[(size_t)(r0 + 8) * ldc + c0]) =
                    make_float2(v10, v11);
            }
        }
    }
}

// ---------------- mask bias prep -------------------------------------------
__global__ void prep_maskb(const int* __restrict__ mask, float* __restrict__ mb)
{
    int i = blockIdx.x * 256 + threadIdx.x;
    if (i < BB * SS) mb[i] = mask[i] ? 0.f : -1e30f;
}

// ---------------- fused flash attention (HMMA, 3xFP16) ---------------------
// grid (S/128, NH, BB), 256 threads = 8 warps, each warp owns 16 q-rows.
// Q tile resident in smem (hi/lo); K/V streamed in 64-row stages,
// cp.async double-buffered. Online softmax in registers.
#define ATT_STR 272                      // 272 % 128 == 16 -> conflict-free
#define ATT_Q_H 0
#define ATT_Q_L (128*ATT_STR)            // 34816
#define ATT_STAGE0 (2*128*ATT_STR)       // 69632
#define ST_KH 0
#define ST_KL (64*ATT_STR)               // 17408
#define ST_VH (2*64*ATT_STR)
#define ST_VL (3*64*ATT_STR)
#define ST_MB (4*64*ATT_STR)             // 69632 (64 floats)
#define ATT_STAGE_SZ (4*64*ATT_STR + 256)   // 69888
#define ATT_SMEM (ATT_STAGE0 + 2*ATT_STAGE_SZ)  // 209408

__global__ __launch_bounds__(256)
void flash_attn(const __half* __restrict__ qh, const __half* __restrict__ ql,
                const __half* __restrict__ kh, const __half* __restrict__ kl,
                const __half* __restrict__ vh, const __half* __restrict__ vl,
                const float* __restrict__ maskb, float* __restrict__ attn)
{
    extern __shared__ __align__(16) unsigned char sm[];
    const uint32_t sb = smem_u32(sm);
    const int tid  = threadIdx.x;
    const int lane = tid & 31;
    const int warp = tid >> 5;
    const int gid  = lane >> 2;
    const int tig  = lane & 3;
    const int qb = blockIdx.x, h = blockIdx.y, b = blockIdx.z;
    const int wm = warp * 16;

    // ---- Q tile async load: 2 arrays x 128 rows x 16 chunks
#pragma unroll
    for (int i = 0; i < 16; i++) {
        const __half* src = (i < 8) ? qh : ql;
        uint32_t abase = (i < 8) ? ATT_Q_H : ATT_Q_L;
        int row = (tid >> 4) + (i & 7) * 16;      // 0..127
        int c16 = tid & 15;
        CP_ASYNC16(sb + abase + row * ATT_STR + c16 * 16,
                   src + ((size_t)(b * SS + qb * 128 + row)) * HH + h * HD + c16 * 8);
    }
    CP_COMMIT();

    auto issue_kv = [&](int it, int stg) {
        uint32_t base = sb + ATT_STAGE0 + stg * ATT_STAGE_SZ;
        int kv0 = it * 64;
#pragma unroll
        for (int i = 0; i < 16; i++) {
            const __half* src = (i < 4) ? kh : (i < 8) ? kl : (i < 12) ? vh : vl;
            uint32_t aoff = (i < 4) ? ST_KH : (i < 8) ? ST_KL
                          : (i < 12) ? ST_VH : ST_VL;
            int row = (tid >> 4) + (i & 3) * 16;  // 0..63
            int c16 = tid & 15;
            CP_ASYNC16(base + aoff + row * ATT_STR + c16 * 16,
                       src + ((size_t)(b * SS + kv0 + row)) * HD + c16 * 8);
        }
        if (tid < 64)
            CP_ASYNC4(base + ST_MB + tid * 4, maskb + b * SS + kv0 + tid);
        CP_COMMIT();
    };

    float oacc[16][4];
#pragma unroll
    for (int i = 0; i < 16; i++)
#pragma unroll
        for (int j = 0; j < 4; j++) oacc[i][j] = 0.f;
    float m0 = -1e30f, m1 = -1e30f, l0 = 0.f, l1 = 0.f;
    const float ascale = 0.08838834764831845f;

    issue_kv(0, 0);

    const uint32_t aoff = (uint32_t)((wm + (lane & 15)) * ATT_STR
                        + ((lane >> 4) & 1) * 16);
    const uint32_t boff = (uint32_t)((((lane >> 4) & 1) * 8 + (lane & 7)) * ATT_STR
                        + ((lane >> 3) & 1) * 16);
    const uint32_t toff0 = (uint32_t)((lane & 15) * ATT_STR
                         + ((lane >> 4) & 1) * 16);

    for (int it = 0; it < 32; it++) {
        const int stg = it & 1;
        if (it + 1 < 32) { issue_kv(it + 1, stg ^ 1); CP_WAIT1(); }
        else             { CP_WAIT0(); }
        __syncthreads();

        const uint32_t stbase = sb + ATT_STAGE0 + stg * ATT_STAGE_SZ;

        // ---- S = Q @ K^T (3xFP16)
        float sacc[8][4];
#pragma unroll
        for (int i = 0; i < 8; i++)
#pragma unroll
            for (int j = 0; j < 4; j++) sacc[i][j] = 0.f;

#pragma unroll
        for (int ks = 0; ks < 8; ks++) {
            const uint32_t ko = ks * 32;
            uint32_t ah[4], al[4];
            LDSM_X4(ah[0], ah[1], ah[2], ah[3], sb + ATT_Q_H + aoff + ko);
            LDSM_X4(al[0], al[1], al[2], al[3], sb + ATT_Q_L + aoff + ko);
#pragma unroll
            for (int np = 0; np < 4; np++) {
                uint32_t bh[4], bl[4];
                uint32_t ba = stbase + np * (16 * ATT_STR) + boff + ko;
                LDSM_X4(bh[0], bh[1], bh[2], bh[3], ba + ST_KH);
                LDSM_X4(bl[0], bl[1], bl[2], bl[3], ba + ST_KL);
                MMA_F16(sacc[2*np],   ah[0], ah[1], ah[2], ah[3], bh[0], bh[1]);
                MMA_F16(sacc[2*np],   ah[0], ah[1], ah[2], ah[3], bl[0], bl[1]);
                MMA_F16(sacc[2*np],   al[0], al[1], al[2], al[3], bh[0], bh[1]);
                MMA_F16(sacc[2*np+1], ah[0], ah[1], ah[2], ah[3], bh[2], bh[3]);
                MMA_F16(sacc[2*np+1], ah[0], ah[1], ah[2], ah[3], bl[2], bl[3]);
                MMA_F16(sacc[2*np+1], al[0], al[1], al[2], al[3], bh[2], bh[3]);
            }
        }

        // ---- scale + mask bias, online softmax (rows gid, gid+8)
        const float* mbp = reinterpret_cast<const float*>(
            sm + (size_t)(ATT_STAGE0 + stg * ATT_STAGE_SZ + ST_MB));
        float tm0 = -1e30f, tm1 = -1e30f;
#pragma unroll
        for (int nf = 0; nf < 8; nf++) {
            float mb0 = mbp[nf * 8 + 2 * tig];
            float mb1 = mbp[nf * 8 + 2 * tig + 1];
            sacc[nf][0] = sacc[nf][0] * ascale + mb0;
            sacc[nf][1] = sacc[nf][1] * ascale + mb1;
            sacc[nf][2] = sacc[nf][2] * ascale + mb0;
            sacc[nf][3] = sacc[nf][3] * ascale + mb1;
            tm0 = fmaxf(tm0, fmaxf(sacc[nf][0], sacc[nf][1]));
            tm1 = fmaxf(tm1, fmaxf(sacc[nf][2], sacc[nf][3]));
        }
        tm0 = fmaxf(tm0, __shfl_xor_sync(~0u, tm0, 1));
        tm0 = fmaxf(tm0, __shfl_xor_sync(~0u, tm0, 2));
        tm1 = fmaxf(tm1, __shfl_xor_sync(~0u, tm1, 1));
        tm1 = fmaxf(tm1, __shfl_xor_sync(~0u, tm1, 2));
        float nm0 = fmaxf(m0, tm0), nm1 = fmaxf(m1, tm1);
        float cor0 = __expf(m0 - nm0), cor1 = __expf(m1 - nm1);
        float rs0 = 0.f, rs1 = 0.f;
#pragma unroll
        for (int nf = 0; nf < 8; nf++) {
            sacc[nf][0] = __expf(sacc[nf][0] - nm0);
            sacc[nf][1] = __expf(sacc[nf][1] - nm0);
            sacc[nf][2] = __expf(sacc[nf][2] - nm1);
            sacc[nf][3] = __expf(sacc[nf][3] - nm1);
            rs0 += sacc[nf][0] + sacc[nf][1];
            rs1 += sacc[nf][2] + sacc[nf][3];
        }
        rs0 += __shfl_xor_sync(~0u, rs0, 1);
        rs0 += __shfl_xor_sync(~0u, rs0, 2);
        rs1 += __shfl_xor_sync(~0u, rs1, 1);
        rs1 += __shfl_xor_sync(~0u, rs1, 2);
        l0 = l0 * cor0 + rs0;  m0 = nm0;
        l1 = l1 * cor1 + rs1;  m1 = nm1;
#pragma unroll
        for (int nf = 0; nf < 16; nf++) {
            oacc[nf][0] *= cor0; oacc[nf][1] *= cor0;
            oacc[nf][2] *= cor1; oacc[nf][3] *= cor1;
        }

        // ---- out += P @ V (3xFP16); P A-frags from score accumulators
#pragma unroll
        for (int kf = 0; kf < 4; kf++) {
            __half e0h = __float2half_rn(sacc[2*kf][0]);
            __half e1h = __float2half_rn(sacc[2*kf][1]);
            __half e2h = __float2half_rn(sacc[2*kf][2]);
            __half e3h = __float2half_rn(sacc[2*kf][3]);
            __half f0h = __float2half_rn(sacc[2*kf+1][0]);
            __half f1h = __float2half_rn(sacc[2*kf+1][1]);
            __half f2h = __float2half_rn(sacc[2*kf+1][2]);
            __half f3h = __float2half_rn(sacc[2*kf+1][3]);
            uint32_t pa0 = h2_as_u32(e0h, e1h), pa1 = h2_as_u32(e2h, e3h);
            uint32_t pa2 = h2_as_u32(f0h, f1h), pa3 = h2_as_u32(f2h, f3h);
            uint32_t qa0 = h2_as_u32(
                __float2half_rn(sacc[2*kf][0] - __half2float(e0h)),
                __float2half_rn(sacc[2*kf][1] - __half2float(e1h)));
            uint32_t qa1 = h2_as_u32(
                __float2half_rn(sacc[2*kf][2] - __half2float(e2h)),
                __float2half_rn(sacc[2*kf][3] - __half2float(e3h)));
            uint32_t qa2 = h2_as_u32(
                __float2half_rn(sacc[2*kf+1][0] - __half2float(f0h)),
                __float2half_rn(sacc[2*kf+1][1] - __half2float(f1h)));
            uint32_t qa3 = h2_as_u32(
                __float2half_rn(sacc[2*kf+1][2] - __half2float(f2h)),
                __float2half_rn(sacc[2*kf+1][3] - __half2float(f3h)));

            uint32_t tadr = stbase + toff0 + kf * (16 * ATT_STR);
#pragma unroll
            for (int np2 = 0; np2 < 8; np2++) {
                uint32_t bh[4], bl[4];
                LDSM_X4_T(bh[0], bh[1], bh[2], bh[3], tadr + ST_VH + np2 * 32);
                LDSM_X4_T(bl[0], bl[1], bl[2], bl[3], tadr + ST_VL + np2 * 32);
                MMA_F16(oacc[2*np2],   pa0, pa1, pa2, pa3, bh[0], bh[1]);
                MMA_F16(oacc[2*np2],   pa0, pa1, pa2, pa3, bl[0], bl[1]);
                MMA_F16(oacc[2*np2],   qa0, qa1, qa2, qa3, bh[0], bh[1]);
                MMA_F16(oacc[2*np2+1], pa0, pa1, pa2, pa3, bh[2], bh[3]);
                MMA_F16(oacc[2*np2+1], pa0, pa1, pa2, pa3, bl[2], bl[3]);
                MMA_F16(oacc[2*np2+1], qa0, qa1, qa2, qa3, bh[2], bh[3]);
            }
        }
        __syncthreads();
    }

    // ---- normalize + write (B,S,H)
    float inv0 = 1.0f / l0, inv1 = 1.0f / l1;
    size_t r0 = (size_t)(b * SS + qb * 128 + wm + gid);
#pragma unroll
    for (int nf = 0; nf < 16; nf++) {
        int col = h * HD + nf * 8 + 2 * tig;
        *reinterpret_cast<float2*>(&attn[r0 * HH + col]) =
            make_float2(oacc[nf][0] * inv0, oacc[nf][1] * inv0);
        *reinterpret_cast<float2*>(&attn[(r0 + 8) * HH + col]) =
            make_float2(oacc[nf][2] * inv1, oacc[nf][3] * inv1);
    }
}

// ---------------- launch ---------------------------------------------------
extern "C" void kernel_launch(void* const* d_in, const int* in_sizes, int n_in,
                              void* d_out, int out_size)
{
    const float* hidden = (const float*)d_in[0];
    const int*   mask   = (const int*)  d_in[1];
    const float* Wq = (const float*)d_in[2];
    const float* bq = (const float*)d_in[3];
    const float* Wk = (const float*)d_in[4];
    const float* bk = (const float*)d_in[5];
    const float* Wv = (const float*)d_in[6];
    const float* bv = (const float*)d_in[7];
    const float* Wo = (const float*)d_in[8];
    const float* bo = (const float*)d_in[9];
    float* out = (float*)d_out;

    __half *qh, *ql, *kh, *kl, *vh, *vl;
    float *attn, *maskb;
    cudaGetSymbolAddress((void**)&qh,    g_qh);
    cudaGetSymbolAddress((void**)&ql,    g_ql);
    cudaGetSymbolAddress((void**)&kh,    g_kh);
    cudaGetSymbolAddress((void**)&kl,    g_kl);
    cudaGetSymbolAddress((void**)&vh,    g_vh);
    cudaGetSymbolAddress((void**)&vl,    g_vl);
    cudaGetSymbolAddress((void**)&attn,  g_attn);
    cudaGetSymbolAddress((void**)&maskb, g_maskb);

    cudaFuncSetAttribute(flash_attn,
        cudaFuncAttributeMaxDynamicSharedMemorySize, ATT_SMEM);

    // projections -> fp16 hi/lo
    gemm_hmma<<<dim3(16, 32), 256>>>(hidden, Wq, bq, nullptr, qh, ql,
                                     HH, HH, HH, HH, 1.f);
    gemm_hmma<<<dim3(1, 32), 256>>>(hidden, Wk, bk, nullptr, kh, kl,
                                    HH, HH, HH, HD, 1.f);
    gemm_hmma<<<dim3(1, 32), 256>>>(hidden, Wv, bv, nullptr, vh, vl,
                                    HH, HH, HH, HD, 1.f);
    prep_maskb<<<(BB*SS)/256, 256>>>(mask, maskb);
    // fused attention
    flash_attn<<<dim3(SS/128, NH, BB), 256, ATT_SMEM>>>(
        qh, ql, kh, kl, vh, vl, maskb, attn);
    // output projection -> fp32 d_out
    gemm_hmma<<<dim3(16, 32), 256>>>(attn, Wo, bo, out, nullptr, nullptr,
                                     HH, HH, HH, HH, 1.f);
}

// round 9
// speedup vs baseline: 5.3824x; 1.4795x over previous
#include <cuda_runtime.h>
#include <cuda_fp16.h>
#include <cstdint>
#include <cstring>

// Problem constants (fixed by the dataset)
#define BB 2
#define SS 2048
#define HH 2048
#define HD 128
#define NH 16
#define MM (BB*SS)   // 4096

// ---------------- scratch (static device globals — no allocation) ----------
__device__ __half g_qh[(size_t)BB*SS*HH];   // Q projection hi (B,S,H)
__device__ __half g_ql[(size_t)BB*SS*HH];   // Q projection lo
__device__ __half g_k [(size_t)BB*SS*HD];   // K plain fp16 (B,S,hd)
__device__ __half g_v [(size_t)BB*SS*HD];   // V plain fp16
__device__ float  g_attn[(size_t)BB*SS*HH]; // attention output (B,S,H)
__device__ float  g_maskb[(size_t)BB*SS];   // mask bias: 0 or -1e30

// ---------------- helpers ---------------------------------------------------
__device__ __forceinline__ uint32_t smem_u32(const void* p) {
    uint32_t a;
    asm("{ .reg .u64 t; cvta.to.shared.u64 t, %1; cvt.u32.u64 %0, t; }"
        : "=r"(a) : "l"(p));
    return a;
}

#define MMA_F16(d, a0, a1, a2, a3, b0, b1) asm volatile( \
    "mma.sync.aligned.m16n8k16.row.col.f32.f16.f16.f32 " \
    "{%0,%1,%2,%3}, {%4,%5,%6,%7}, {%8,%9}, {%0,%1,%2,%3};" \
    : "+f"((d)[0]), "+f"((d)[1]), "+f"((d)[2]), "+f"((d)[3]) \
    : "r"(a0), "r"(a1), "r"(a2), "r"(a3), "r"(b0), "r"(b1))

#define LDSM_X4(r0, r1, r2, r3, addr) asm volatile( \
    "ldmatrix.sync.aligned.m8n8.x4.shared.b16 {%0,%1,%2,%3}, [%4];" \
    : "=r"(r0), "=r"(r1), "=r"(r2), "=r"(r3) : "r"(addr))

#define LDSM_X4_T(r0, r1, r2, r3, addr) asm volatile( \
    "ldmatrix.sync.aligned.m8n8.x4.trans.shared.b16 {%0,%1,%2,%3}, [%4];" \
    : "=r"(r0), "=r"(r1), "=r"(r2), "=r"(r3) : "r"(addr))

#define CP_ASYNC16(s, g) asm volatile( \
    "cp.async.ca.shared.global [%0], [%1], 16;" :: "r"(s), "l"(g))
#define CP_ASYNC4(s, g) asm volatile( \
    "cp.async.ca.shared.global [%0], [%1], 4;" :: "r"(s), "l"(g))
#define CP_COMMIT() asm volatile("cp.async.commit_group;")
#define CP_WAIT0() asm volatile("cp.async.wait_group 0;")
#define CP_WAIT1() asm volatile("cp.async.wait_group 1;")

__device__ __forceinline__ uint32_t h2_as_u32(__half x, __half y) {
    __half2 t = __halves2half2(x, y);
    uint32_t u; memcpy(&u, &t, 4); return u;
}

// ---------------- fp16x2 mma.sync NT GEMM ----------------------------------
// C[m][n] = alpha * sum_k A[m][k]*B[n][k] (+ bias[n])
// A (activations) split hi/lo in smem; B (weights) plain fp16.
// 2 MMAs per product. Output: fp32 C, or fp16 hi/lo (Ch,Cl), or plain (Ch).
#define RSTR 80
#define T_AH 0
#define T_AL 10240
#define T_BH 20480

__global__ __launch_bounds__(256)
void gemm_hmma(const float* __restrict__ A, const float* __restrict__ Bw,
               const float* __restrict__ bias, float* __restrict__ C,
               __half* __restrict__ Ch, __half* __restrict__ Cl,
               int K, long long lda, long long ldb, long long ldc,
               float alpha)
{
    __shared__ __align__(16) unsigned char smem[30720];
    const uint32_t sb = smem_u32(smem);

    const int tid  = threadIdx.x;
    const int lane = tid & 31;
    const int warp = tid >> 5;
    const int gid  = lane >> 2;
    const int tig  = lane & 3;
    const int wm   = (warp >> 2) * 64;
    const int wn   = (warp & 3) * 32;

    const int rowBase = blockIdx.y * 128;
    const int colBase = blockIdx.x * 128;

    float acc[4][4][4];
#pragma unroll
    for (int i = 0; i < 4; i++)
#pragma unroll
        for (int j = 0; j < 4; j++)
#pragma unroll
            for (int c = 0; c < 4; c++) acc[i][j][c] = 0.f;

    const uint32_t aBase = sb + (uint32_t)((wm + (lane & 15)) * RSTR
                          + ((lane >> 4) & 1) * 16);
    const uint32_t bBase = sb + (uint32_t)((wn + ((lane >> 4) & 1) * 8
                          + (lane & 7)) * RSTR + ((lane >> 3) & 1) * 16);

    const int ldRow = tid >> 3;
    const int ldF4  = tid & 7;
    float4 pa[4], pb[4];
    auto loadChunk = [&](int c) {
        const int kt = c << 5;
#pragma unroll
        for (int i = 0; i < 4; i++) {
            int row = ldRow + i * 32;
            pa[i] = *reinterpret_cast<const float4*>(
                &A[(size_t)(rowBase + row) * lda + kt + ldF4 * 4]);
            pb[i] = *reinterpret_cast<const float4*>(
                &Bw[(size_t)(colBase + row) * ldb + kt + ldF4 * 4]);
        }
    };
    auto stsChunk = [&]() {
#pragma unroll
        for (int i = 0; i < 4; i++) {
            int row = ldRow + i * 32;
            uint32_t off = (uint32_t)(row * RSTR + ldF4 * 8);
            {
                float4 v = pa[i];
                __half hx = __float2half_rn(v.x), hy = __float2half_rn(v.y);
                __half hz = __float2half_rn(v.z), hw = __float2half_rn(v.w);
                *reinterpret_cast<uint2*>(smem + T_AH + off) =
                    make_uint2(h2_as_u32(hx, hy), h2_as_u32(hz, hw));
                *reinterpret_cast<uint2*>(smem + T_AL + off) = make_uint2(
                    h2_as_u32(__float2half_rn(v.x - __half2float(hx)),
                              __float2half_rn(v.y - __half2float(hy))),
                    h2_as_u32(__float2half_rn(v.z - __half2float(hz)),
                              __float2half_rn(v.w - __half2float(hw))));
            }
            {
                float4 v = pb[i];
                *reinterpret_cast<uint2*>(smem + T_BH + off) = make_uint2(
                    h2_as_u32(__float2half_rn(v.x), __float2half_rn(v.y)),
                    h2_as_u32(__float2half_rn(v.z), __float2half_rn(v.w)));
            }
        }
    };

    const int nchunks = K >> 5;
    loadChunk(0);
    for (int c = 0; c < nchunks; c++) {
        stsChunk();
        __syncthreads();
        if (c + 1 < nchunks) loadChunk(c + 1);

#pragma unroll
        for (int ks = 0; ks < 2; ks++) {
            const uint32_t ko = ks * 32;
            uint32_t ah[4][4], al[4][4], bh[4][2];
#pragma unroll
            for (int mf = 0; mf < 4; mf++) {
                uint32_t a = aBase + mf * (16 * RSTR) + ko;
                LDSM_X4(ah[mf][0], ah[mf][1], ah[mf][2], ah[mf][3], a + T_AH);
                LDSM_X4(al[mf][0], al[mf][1], al[mf][2], al[mf][3], a + T_AL);
            }
#pragma unroll
            for (int nfp = 0; nfp < 2; nfp++) {
                uint32_t b = bBase + nfp * (16 * RSTR) + ko;
                LDSM_X4(bh[2*nfp][0], bh[2*nfp][1], bh[2*nfp+1][0], bh[2*nfp+1][1],
                        b + T_BH);
            }
#pragma unroll
            for (int mf = 0; mf < 4; mf++)
#pragma unroll
                for (int nf = 0; nf < 4; nf++) {
                    MMA_F16(acc[mf][nf], ah[mf][0], ah[mf][1], ah[mf][2], ah[mf][3],
                            bh[nf][0], bh[nf][1]);
                    MMA_F16(acc[mf][nf], al[mf][0], al[mf][1], al[mf][2], al[mf][3],
                            bh[nf][0], bh[nf][1]);
                }
        }
        __syncthreads();
    }

#pragma unroll
    for (int mf = 0; mf < 4; mf++) {
        int r0 = rowBase + wm + mf * 16 + gid;
#pragma unroll
        for (int nf = 0; nf < 4; nf++) {
            int c0 = colBase + wn + nf * 8 + 2 * tig;
            float b0 = 0.f, b1 = 0.f;
            if (bias) { b0 = bias[c0]; b1 = bias[c0 + 1]; }
            float v00 = acc[mf][nf][0] * alpha + b0;
            float v01 = acc[mf][nf][1] * alpha + b1;
            float v10 = acc[mf][nf][2] * alpha + b0;
            float v11 = acc[mf][nf][3] * alpha + b1;
            if (Ch && Cl) {          // split fp16 hi/lo output (Q)
                __half h00 = __float2half_rn(v00), h01 = __float2half_rn(v01);
                __half h10 = __float2half_rn(v10), h11 = __float2half_rn(v11);
                *reinterpret_cast<uint32_t*>(&Ch[(size_t)r0 * ldc + c0]) =
                    h2_as_u32(h00, h01);
                *reinterpret_cast<uint32_t*>(&Ch[(size_t)(r0 + 8) * ldc + c0]) =
                    h2_as_u32(h10, h11);
                *reinterpret_cast<uint32_t*>(&Cl[(size_t)r0 * ldc + c0]) =
                    h2_as_u32(__float2half_rn(v00 - __half2float(h00)),
                              __float2half_rn(v01 - __half2float(h01)));
                *reinterpret_cast<uint32_t*>(&Cl[(size_t)(r0 + 8) * ldc + c0]) =
                    h2_as_u32(__float2half_rn(v10 - __half2float(h10)),
                              __float2half_rn(v11 - __half2float(h11)));
            } else if (Ch) {         // plain fp16 output (K/V)
                *reinterpret_cast<uint32_t*>(&Ch[(size_t)r0 * ldc + c0]) =
                    h2_as_u32(__float2half_rn(v00), __float2half_rn(v01));
                *reinterpret_cast<uint32_t*>(&Ch[(size_t)(r0 + 8) * ldc + c0]) =
                    h2_as_u32(__float2half_rn(v10), __float2half_rn(v11));
            } else {                 // fp32 output
                *reinterpret_cast<float2*>(&C[(size_t)r0 * ldc + c0]) =
                    make_float2(v00, v01);
                *reinterpret_cast<float2*>(&C[(size_t)(r0 + 8) * ldc + c0]) =
                    make_float2(v10, v11);
            }
        }
    }
}

// ---------------- mask bias prep -------------------------------------------
__global__ void prep_maskb(const int* __restrict__ mask, float* __restrict__ mb)
{
    int i = blockIdx.x * 256 + threadIdx.x;
    if (i < BB * SS) mb[i] = mask[i] ? 0.f : -1e30f;
}

// ---------------- fused flash attention (HMMA, 2-pass fp16) ----------------
// grid (S/128, NH, BB), 256 threads = 8 warps, each warp owns 16 q-rows.
// Q resident hi/lo; K,V plain fp16, streamed 64-row stages double-buffered.
// QK^T = qh*k + ql*k; PV = ph*v + pl*v (P split in registers).
#define ATT_STR 272                      // 272 % 128 == 16 -> conflict-free
#define ATT_Q_H 0
#define ATT_Q_L (128*ATT_STR)            // 34816
#define ATT_STAGE0 (2*128*ATT_STR)       // 69632
#define ST_K 0
#define ST_V (64*ATT_STR)                // 17408
#define ST_MB (2*64*ATT_STR)             // 34816 (64 floats)
#define ATT_STAGE_SZ (2*64*ATT_STR + 256)   // 35072
#define ATT_SMEM (ATT_STAGE0 + 2*ATT_STAGE_SZ)  // 139776

__global__ __launch_bounds__(256)
void flash_attn(const __half* __restrict__ qh, const __half* __restrict__ ql,
                const __half* __restrict__ kk, const __half* __restrict__ vv,
                const float* __restrict__ maskb, float* __restrict__ attn)
{
    extern __shared__ __align__(16) unsigned char sm[];
    const uint32_t sb = smem_u32(sm);
    const int tid  = threadIdx.x;
    const int lane = tid & 31;
    const int warp = tid >> 5;
    const int gid  = lane >> 2;
    const int tig  = lane & 3;
    const int qb = blockIdx.x, h = blockIdx.y, b = blockIdx.z;
    const int wm = warp * 16;

    // ---- Q tile async load: 2 arrays x 128 rows
#pragma unroll
    for (int i = 0; i < 16; i++) {
        const __half* src = (i < 8) ? qh : ql;
        uint32_t abase = (i < 8) ? ATT_Q_H : ATT_Q_L;
        int row = (tid >> 4) + (i & 7) * 16;
        int c16 = tid & 15;
        CP_ASYNC16(sb + abase + row * ATT_STR + c16 * 16,
                   src + ((size_t)(b * SS + qb * 128 + row)) * HH + h * HD + c16 * 8);
    }
    CP_COMMIT();

    auto issue_kv = [&](int it, int stg) {
        uint32_t base = sb + ATT_STAGE0 + stg * ATT_STAGE_SZ;
        int kv0 = it * 64;
#pragma unroll
        for (int i = 0; i < 8; i++) {
            const __half* src = (i < 4) ? kk : vv;
            uint32_t aoff = (i < 4) ? ST_K : ST_V;
            int row = (tid >> 4) + (i & 3) * 16;
            int c16 = tid & 15;
            CP_ASYNC16(base + aoff + row * ATT_STR + c16 * 16,
                       src + ((size_t)(b * SS + kv0 + row)) * HD + c16 * 8);
        }
        if (tid < 64)
            CP_ASYNC4(base + ST_MB + tid * 4, maskb + b * SS + kv0 + tid);
        CP_COMMIT();
    };

    float oacc[16][4];
#pragma unroll
    for (int i = 0; i < 16; i++)
#pragma unroll
        for (int j = 0; j < 4; j++) oacc[i][j] = 0.f;
    float m0 = -1e30f, m1 = -1e30f, l0 = 0.f, l1 = 0.f;
    const float ascale = 0.08838834764831845f;

    issue_kv(0, 0);

    const uint32_t aoff = (uint32_t)((wm + (lane & 15)) * ATT_STR
                        + ((lane >> 4) & 1) * 16);
    const uint32_t boff = (uint32_t)((((lane >> 4) & 1) * 8 + (lane & 7)) * ATT_STR
                        + ((lane >> 3) & 1) * 16);
    const uint32_t toff0 = (uint32_t)((lane & 15) * ATT_STR
                         + ((lane >> 4) & 1) * 16);

    for (int it = 0; it < 32; it++) {
        const int stg = it & 1;
        if (it + 1 < 32) { issue_kv(it + 1, stg ^ 1); CP_WAIT1(); }
        else             { CP_WAIT0(); }
        __syncthreads();

        const uint32_t stbase = sb + ATT_STAGE0 + stg * ATT_STAGE_SZ;

        // ---- S = Q @ K^T (qh*k + ql*k)
        float sacc[8][4];
#pragma unroll
        for (int i = 0; i < 8; i++)
#pragma unroll
            for (int j = 0; j < 4; j++) sacc[i][j] = 0.f;

#pragma unroll
        for (int ks = 0; ks < 8; ks++) {
            const uint32_t ko = ks * 32;
            uint32_t ah[4], al[4];
            LDSM_X4(ah[0], ah[1], ah[2], ah[3], sb + ATT_Q_H + aoff + ko);
            LDSM_X4(al[0], al[1], al[2], al[3], sb + ATT_Q_L + aoff + ko);
#pragma unroll
            for (int np = 0; np < 4; np++) {
                uint32_t bh[4];
                uint32_t ba = stbase + np * (16 * ATT_STR) + boff + ko;
                LDSM_X4(bh[0], bh[1], bh[2], bh[3], ba + ST_K);
                MMA_F16(sacc[2*np],   ah[0], ah[1], ah[2], ah[3], bh[0], bh[1]);
                MMA_F16(sacc[2*np],   al[0], al[1], al[2], al[3], bh[0], bh[1]);
                MMA_F16(sacc[2*np+1], ah[0], ah[1], ah[2], ah[3], bh[2], bh[3]);
                MMA_F16(sacc[2*np+1], al[0], al[1], al[2], al[3], bh[2], bh[3]);
            }
        }

        // ---- scale + mask bias, online softmax (rows gid, gid+8)
        const float* mbp = reinterpret_cast<const float*>(
            sm + (size_t)(ATT_STAGE0 + stg * ATT_STAGE_SZ + ST_MB));
        float tm0 = -1e30f, tm1 = -1e30f;
#pragma unroll
        for (int nf = 0; nf < 8; nf++) {
            float mb0 = mbp[nf * 8 + 2 * tig];
            float mb1 = mbp[nf * 8 + 2 * tig + 1];
            sacc[nf][0] = sacc[nf][0] * ascale + mb0;
            sacc[nf][1] = sacc[nf][1] * ascale + mb1;
            sacc[nf][2] = sacc[nf][2] * ascale + mb0;
            sacc[nf][3] = sacc[nf][3] * ascale + mb1;
            tm0 = fmaxf(tm0, fmaxf(sacc[nf][0], sacc[nf][1]));
            tm1 = fmaxf(tm1, fmaxf(sacc[nf][2], sacc[nf][3]));
        }
        tm0 = fmaxf(tm0, __shfl_xor_sync(~0u, tm0, 1));
        tm0 = fmaxf(tm0, __shfl_xor_sync(~0u, tm0, 2));
        tm1 = fmaxf(tm1, __shfl_xor_sync(~0u, tm1, 1));
        tm1 = fmaxf(tm1, __shfl_xor_sync(~0u, tm1, 2));
        float nm0 = fmaxf(m0, tm0), nm1 = fmaxf(m1, tm1);
        float cor0 = __expf(m0 - nm0), cor1 = __expf(m1 - nm1);
        float rs0 = 0.f, rs1 = 0.f;
#pragma unroll
        for (int nf = 0; nf < 8; nf++) {
            sacc[nf][0] = __expf(sacc[nf][0] - nm0);
            sacc[nf][1] = __expf(sacc[nf][1] - nm0);
            sacc[nf][2] = __expf(sacc[nf][2] - nm1);
            sacc[nf][3] = __expf(sacc[nf][3] - nm1);
            rs0 += sacc[nf][0] + sacc[nf][1];
            rs1 += sacc[nf][2] + sacc[nf][3];
        }
        rs0 += __shfl_xor_sync(~0u, rs0, 1);
        rs0 += __shfl_xor_sync(~0u, rs0, 2);
        rs1 += __shfl_xor_sync(~0u, rs1, 1);
        rs1 += __shfl_xor_sync(~0u, rs1, 2);
        l0 = l0 * cor0 + rs0;  m0 = nm0;
        l1 = l1 * cor1 + rs1;  m1 = nm1;
#pragma unroll
        for (int nf = 0; nf < 16; nf++) {
            oacc[nf][0] *= cor0; oacc[nf][1] *= cor0;
            oacc[nf][2] *= cor1; oacc[nf][3] *= cor1;
        }

        // ---- out += P @ V (ph*v + pl*v)
#pragma unroll
        for (int kf = 0; kf < 4; kf++) {
            __half e0h = __float2half_rn(sacc[2*kf][0]);
            __half e1h = __float2half_rn(sacc[2*kf][1]);
            __half e2h = __float2half_rn(sacc[2*kf][2]);
            __half e3h = __float2half_rn(sacc[2*kf][3]);
            __half f0h = __float2half_rn(sacc[2*kf+1][0]);
            __half f1h = __float2half_rn(sacc[2*kf+1][1]);
            __half f2h = __float2half_rn(sacc[2*kf+1][2]);
            __half f3h = __float2half_rn(sacc[2*kf+1][3]);
            uint32_t pa0 = h2_as_u32(e0h, e1h), pa1 = h2_as_u32(e2h, e3h);
            uint32_t pa2 = h2_as_u32(f0h, f1h), pa3 = h2_as_u32(f2h, f3h);
            uint32_t qa0 = h2_as_u32(
                __float2half_rn(sacc[2*kf][0] - __half2float(e0h)),
                __float2half_rn(sacc[2*kf][1] - __half2float(e1h)));
            uint32_t qa1 = h2_as_u32(
                __float2half_rn(sacc[2*kf][2] - __half2float(e2h)),
                __float2half_rn(sacc[2*kf][3] - __half2float(e3h)));
            uint32_t qa2 = h2_as_u32(
                __float2half_rn(sacc[2*kf+1][0] - __half2float(f0h)),
                __float2half_rn(sacc[2*kf+1][1] - __half2float(f1h)));
            uint32_t qa3 = h2_as_u32(
                __float2half_rn(sacc[2*kf+1][2] - __half2float(f2h)),
                __float2half_rn(sacc[2*kf+1][3] - __half2float(f3h)));

            uint32_t tadr = stbase + toff0 + kf * (16 * ATT_STR);
#pragma unroll
            for (int np2 = 0; np2 < 8; np2++) {
                uint32_t bh[4];
                LDSM_X4_T(bh[0], bh[1], bh[2], bh[3], tadr + ST_V + np2 * 32);
                MMA_F16(oacc[2*np2],   pa0, pa1, pa2, pa3, bh[0], bh[1]);
                MMA_F16(oacc[2*np2],   qa0, qa1, qa2, qa3, bh[0], bh[1]);
                MMA_F16(oacc[2*np2+1], pa0, pa1, pa2, pa3, bh[2], bh[3]);
                MMA_F16(oacc[2*np2+1], qa0, qa1, qa2, qa3, bh[2], bh[3]);
            }
        }
        __syncthreads();
    }

    // ---- normalize + write (B,S,H)
    float inv0 = 1.0f / l0, inv1 = 1.0f / l1;
    size_t r0 = (size_t)(b * SS + qb * 128 + wm + gid);
#pragma unroll
    for (int nf = 0; nf < 16; nf++) {
        int col = h * HD + nf * 8 + 2 * tig;
        *reinterpret_cast<float2*>(&attn[r0 * HH + col]) =
            make_float2(oacc[nf][0] * inv0, oacc[nf][1] * inv0);
        *reinterpret_cast<float2*>(&attn[(r0 + 8) * HH + col]) =
            make_float2(oacc[nf][2] * inv1, oacc[nf][3] * inv1);
    }
}

// ---------------- launch ---------------------------------------------------
extern "C" void kernel_launch(void* const* d_in, const int* in_sizes, int n_in,
                              void* d_out, int out_size)
{
    const float* hidden = (const float*)d_in[0];
    const int*   mask   = (const int*)  d_in[1];
    const float* Wq = (const float*)d_in[2];
    const float* bq = (const float*)d_in[3];
    const float* Wk = (const float*)d_in[4];
    const float* bk = (const float*)d_in[5];
    const float* Wv = (const float*)d_in[6];
    const float* bv = (const float*)d_in[7];
    const float* Wo = (const float*)d_in[8];
    const float* bo = (const float*)d_in[9];
    float* out = (float*)d_out;

    __half *qh, *ql, *k, *v;
    float *attn, *maskb;
    cudaGetSymbolAddress((void**)&qh,    g_qh);
    cudaGetSymbolAddress((void**)&ql,    g_ql);
    cudaGetSymbolAddress((void**)&k,     g_k);
    cudaGetSymbolAddress((void**)&v,     g_v);
    cudaGetSymbolAddress((void**)&attn,  g_attn);
    cudaGetSymbolAddress((void**)&maskb, g_maskb);

    cudaFuncSetAttribute(flash_attn,
        cudaFuncAttributeMaxDynamicSharedMemorySize, ATT_SMEM);

    // projections
    gemm_hmma<<<dim3(16, 32), 256>>>(hidden, Wq, bq, nullptr, qh, ql,
                                     HH, HH, HH, HH, 1.f);
    gemm_hmma<<<dim3(1, 32), 256>>>(hidden, Wk, bk, nullptr, k, nullptr,
                                    HH, HH, HH, HD, 1.f);
    gemm_hmma<<<dim3(1, 32), 256>>>(hidden, Wv, bv, nullptr, v, nullptr,
                                    HH, HH, HH, HD, 1.f);
    prep_maskb<<<(BB*SS)/256, 256>>>(mask, maskb);
    // fused attention
    flash_attn<<<dim3(SS/128, NH, BB), 256, ATT_SMEM>>>(
        qh, ql, k, v, maskb, attn);
    // output projection -> fp32 d_out
    gemm_hmma<<<dim3(16, 32), 256>>>(attn, Wo, bo, out, nullptr, nullptr,
                                     HH, HH, HH, HH, 1.f);
}